// round 3
// baseline (speedup 1.0000x reference)
#include <cuda_runtime.h>
#include <cstdint>

// ---------------------------------------------------------------------------
// SAGEMean3: out = relu( [x | mean_in | mean_out] @ W + b )
//   x:  [N=50000, 128] f32
//   edge_index: [2, E=600000]  (int64 in reference; harness may pass int32)
//   W:  [384, 1024] f32,  b: [1024] f32
//   out:[50000, 1024] f32
// ---------------------------------------------------------------------------

#define IN_DIM    128
#define K_DIM     384           // 3 * IN_DIM
#define OUT_DIM   1024
#define N_MAX     50000

__device__ __align__(16) float g_H[(size_t)N_MAX * K_DIM];   // concat matrix scratch
__device__ __align__(16) float g_cnt[2 * N_MAX];             // [0:N) in-deg, [N:2N) out-deg
__device__ int g_idx64;                                      // 1 if edge buffer is int64

// ---------------------------------------------------------------------------
// K0: detect index dtype on-device (graph-capture safe; deterministic).
// int64 data with valid indices: every 8-byte word is in [0, n).
// int32 data misread as int64: lo + hi*2^32 >= n almost immediately.
// ---------------------------------------------------------------------------
__global__ void detect_kernel(const void* __restrict__ ei, int n, int E)
{
    const long long* p = (const long long*)ei;
    int lim = 2 * E < 1024 ? 2 * E : 1024;
    int is64 = 1;
    for (int i = 0; i < lim; i++) {
        long long v = p[i];
        if (v < 0 || v >= n) { is64 = 0; break; }
    }
    g_idx64 = is64;
}

// ---------------------------------------------------------------------------
// K1: H[:,0:128] = x ; H[:,128:384] = 0 ; counts = 0
// ---------------------------------------------------------------------------
__global__ void init_kernel(const float* __restrict__ x, int n)
{
    const size_t total = (size_t)n * 96;   // 96 float4 per row
    for (size_t i = (size_t)blockIdx.x * blockDim.x + threadIdx.x;
         i < total; i += (size_t)gridDim.x * blockDim.x) {
        size_t row = i / 96;
        int    c4  = (int)(i % 96);
        float4 v = make_float4(0.f, 0.f, 0.f, 0.f);
        if (c4 < 32)
            v = *(const float4*)&x[row * IN_DIM + c4 * 4];
        *(float4*)&g_H[row * K_DIM + c4 * 4] = v;
    }
    size_t tid = (size_t)blockIdx.x * blockDim.x + threadIdx.x;
    if (tid < (size_t)(2 * n)) g_cnt[tid] = 0.f;
}

// ---------------------------------------------------------------------------
// K2: edge scatter. One warp per edge; lane l handles floats [4l, 4l+4).
// dst_buf == nullptr means packed [2,E]: dst starts E elements (of the
// detected dtype) after src_buf.
// ---------------------------------------------------------------------------
__device__ __forceinline__ void atomic_add_v4(float* p, float4 v)
{
#if __CUDA_ARCH__ >= 900
    atomicAdd((float4*)p, v);
#else
    atomicAdd(p + 0, v.x); atomicAdd(p + 1, v.y);
    atomicAdd(p + 2, v.z); atomicAdd(p + 3, v.w);
#endif
}

__global__ void scatter_kernel(const float* __restrict__ x,
                               const void* __restrict__ src_buf,
                               const void* __restrict__ dst_buf,
                               int n, int E)
{
    int warp = (int)(((size_t)blockIdx.x * blockDim.x + threadIdx.x) >> 5);
    int lane = threadIdx.x & 31;
    if (warp >= E) return;

    long long s, d;
    if (g_idx64) {
        const long long* sp = (const long long*)src_buf;
        const long long* dp = dst_buf ? (const long long*)dst_buf : sp + E;
        s = sp[warp];
        d = dp[warp];
    } else {
        const int* sp = (const int*)src_buf;
        const int* dp = dst_buf ? (const int*)dst_buf : sp + E;
        s = sp[warp];
        d = dp[warp];
    }
    if ((unsigned long long)s >= (unsigned long long)n ||
        (unsigned long long)d >= (unsigned long long)n) return;

    float4 xs = *(const float4*)&x[(size_t)s * IN_DIM + lane * 4];
    float4 xd = *(const float4*)&x[(size_t)d * IN_DIM + lane * 4];

    // src -> dst messages: mean_in slot of dst  (cols 128..255)
    atomic_add_v4(&g_H[(size_t)d * K_DIM + 128 + lane * 4], xs);
    // dst -> src messages: mean_out slot of src (cols 256..383)
    atomic_add_v4(&g_H[(size_t)s * K_DIM + 256 + lane * 4], xd);

    if (lane == 0) {
        atomicAdd(&g_cnt[d], 1.0f);
        atomicAdd(&g_cnt[n + s], 1.0f);
    }
}

// ---------------------------------------------------------------------------
// K3: divide the two aggregate blocks by clamped degree.
// ---------------------------------------------------------------------------
__global__ void normalize_kernel(int n)
{
    const size_t total = (size_t)n * 64;   // 64 float4 per row (cols 128..383)
    for (size_t i = (size_t)blockIdx.x * blockDim.x + threadIdx.x;
         i < total; i += (size_t)gridDim.x * blockDim.x) {
        size_t row = i / 64;
        int    j   = (int)(i % 64);
        float  cnt = (j < 32) ? g_cnt[row] : g_cnt[n + row];
        float  inv = 1.0f / fmaxf(cnt, 1.0f);
        float4* p = (float4*)&g_H[row * K_DIM + 128 + j * 4];
        float4 v = *p;
        v.x *= inv; v.y *= inv; v.z *= inv; v.w *= inv;
        *p = v;
    }
}

// ---------------------------------------------------------------------------
// K4: SGEMM  out[M,1024] = relu(g_H[M,384] @ W[384,1024] + b)
// 128x128 tile, BK=8, 256 threads, 8x8 micro-tile.
// ---------------------------------------------------------------------------
#define BM 128
#define BN 128
#define BK 8
#define TM 8
#define TN 8

__global__ __launch_bounds__(256, 2)
void gemm_kernel(const float* __restrict__ W,
                 const float* __restrict__ bias,
                 float* __restrict__ out, int M)
{
    __shared__ float As[BK][BM];
    __shared__ float Bs[BK][BN];

    const int bn = blockIdx.x;
    const int bm = blockIdx.y;
    const int tid = threadIdx.x;
    const int tx = tid & 15;
    const int ty = tid >> 4;

    const int rowBase = bm * BM;
    const int colBase = bn * BN;

    const int aRow  = tid >> 1;            // 0..127
    const int aCol4 = (tid & 1) * 4;       // 0 or 4
    const int bRow  = tid >> 5;            // 0..7
    const int bCol4 = (tid & 31) * 4;      // 0..124

    float acc[TM][TN];
    #pragma unroll
    for (int i = 0; i < TM; i++)
        #pragma unroll
        for (int j = 0; j < TN; j++) acc[i][j] = 0.f;

    for (int k0 = 0; k0 < K_DIM; k0 += BK) {
        float4 av = make_float4(0.f, 0.f, 0.f, 0.f);
        int gRow = rowBase + aRow;
        if (gRow < M)
            av = *(const float4*)&g_H[(size_t)gRow * K_DIM + k0 + aCol4];
        As[aCol4 + 0][aRow] = av.x;
        As[aCol4 + 1][aRow] = av.y;
        As[aCol4 + 2][aRow] = av.z;
        As[aCol4 + 3][aRow] = av.w;

        *(float4*)&Bs[bRow][bCol4] =
            *(const float4*)&W[(size_t)(k0 + bRow) * OUT_DIM + colBase + bCol4];

        __syncthreads();

        #pragma unroll
        for (int k = 0; k < BK; k++) {
            float a[TM], bb[TN];
            float4 a0 = *(const float4*)&As[k][ty * TM + 0];
            float4 a1 = *(const float4*)&As[k][ty * TM + 4];
            a[0]=a0.x; a[1]=a0.y; a[2]=a0.z; a[3]=a0.w;
            a[4]=a1.x; a[5]=a1.y; a[6]=a1.z; a[7]=a1.w;
            float4 b0 = *(const float4*)&Bs[k][tx * TN + 0];
            float4 b1 = *(const float4*)&Bs[k][tx * TN + 4];
            bb[0]=b0.x; bb[1]=b0.y; bb[2]=b0.z; bb[3]=b0.w;
            bb[4]=b1.x; bb[5]=b1.y; bb[6]=b1.z; bb[7]=b1.w;
            #pragma unroll
            for (int i = 0; i < TM; i++)
                #pragma unroll
                for (int j = 0; j < TN; j++)
                    acc[i][j] = fmaf(a[i], bb[j], acc[i][j]);
        }
        __syncthreads();
    }

    #pragma unroll
    for (int i = 0; i < TM; i++) {
        int gRow = rowBase + ty * TM + i;
        if (gRow >= M) continue;
        #pragma unroll
        for (int j = 0; j < TN; j += 4) {
            int gc = colBase + tx * TN + j;
            float4 bv = *(const float4*)&bias[gc];
            float4 v;
            v.x = fmaxf(acc[i][j + 0] + bv.x, 0.f);
            v.y = fmaxf(acc[i][j + 1] + bv.y, 0.f);
            v.z = fmaxf(acc[i][j + 2] + bv.z, 0.f);
            v.w = fmaxf(acc[i][j + 3] + bv.w, 0.f);
            *(float4*)&out[(size_t)gRow * OUT_DIM + gc] = v;
        }
    }
}

// ---------------------------------------------------------------------------
// launch — robust to packed [2,E] edge_index OR split src/dst, int32 OR int64
// ---------------------------------------------------------------------------
extern "C" void kernel_launch(void* const* d_in, const int* in_sizes, int n_in,
                              void* d_out, int out_size)
{
    const float* x = (const float*)d_in[0];
    const int n = in_sizes[0] / IN_DIM;    // 50000
    float* out = (float*)d_out;

    const float* W;
    const float* b;
    const void* src_buf;
    const void* dst_buf;
    int E;

    if (n_in >= 5) {
        // layout: x, src, dst, W, b
        E = in_sizes[1];
        src_buf = d_in[1];
        dst_buf = d_in[2];
        W = (const float*)d_in[3];
        b = (const float*)d_in[4];
    } else {
        // layout: x, edge_index[2,E], W, b (packed; dst offset resolved on
        // device after dtype detection)
        E = in_sizes[1] / 2;
        src_buf = d_in[1];
        dst_buf = nullptr;
        W = (const float*)d_in[2];
        b = (const float*)d_in[3];
    }

    detect_kernel<<<1, 1>>>(d_in[1], n, E);
    {
        size_t total = (size_t)n * 96;
        init_kernel<<<(int)((total + 255) / 256), 256>>>(x, n);
    }
    {
        long long threads = (long long)E * 32;
        scatter_kernel<<<(int)((threads + 255) / 256), 256>>>(x, src_buf, dst_buf, n, E);
    }
    {
        size_t total = (size_t)n * 64;
        normalize_kernel<<<(int)((total + 255) / 256), 256>>>(n);
    }
    {
        dim3 grid(OUT_DIM / BN, (n + BM - 1) / BM);
        gemm_kernel<<<grid, 256>>>(W, b, out, n);
    }
}

// round 4
// speedup vs baseline: 1.6439x; 1.6439x over previous
#include <cuda_runtime.h>
#include <cuda_bf16.h>
#include <cstdint>

// ---------------------------------------------------------------------------
// SAGEMean3: out = relu( [x | mean_in | mean_out] @ W + b )
//   x: [50000,128] f32, edge_index: [2,600000] (int64 or int32),
//   W: [384,1024] f32, b: [1024] f32, out: [50000,1024] f32
// ---------------------------------------------------------------------------

#define IN_DIM    128
#define K_DIM     384
#define OUT_DIM   1024
#define N_MAX     50000

__device__ __align__(16) float g_H[(size_t)N_MAX * K_DIM];
__device__ __align__(16) float g_cnt[2 * N_MAX];
__device__ int g_idx64;

// ---------------------------------------------------------------------------
// K0: detect index dtype (parallel — the R3 version was 1 serial thread).
// ---------------------------------------------------------------------------
__global__ void detect_kernel(const long long* __restrict__ p, int n, int E)
{
    __shared__ int ok;
    if (threadIdx.x == 0) ok = 1;
    __syncthreads();
    int lim = 2 * E < 2048 ? 2 * E : 2048;   // first 16KB; safe for both dtypes
    for (int i = threadIdx.x; i < lim; i += blockDim.x) {
        long long v = p[i];
        if (v < 0 || v >= n) ok = 0;         // benign race: all writers write 0
    }
    __syncthreads();
    if (threadIdx.x == 0) g_idx64 = ok;
}

// ---------------------------------------------------------------------------
// K1: H[:,0:128] = x ; H[:,128:384] = 0 ; counts = 0
// ---------------------------------------------------------------------------
__global__ void init_kernel(const float* __restrict__ x, int n)
{
    const size_t total = (size_t)n * 96;
    for (size_t i = (size_t)blockIdx.x * blockDim.x + threadIdx.x;
         i < total; i += (size_t)gridDim.x * blockDim.x) {
        size_t row = i / 96;
        int    c4  = (int)(i % 96);
        float4 v = make_float4(0.f, 0.f, 0.f, 0.f);
        if (c4 < 32)
            v = *(const float4*)&x[row * IN_DIM + c4 * 4];
        *(float4*)&g_H[row * K_DIM + c4 * 4] = v;
    }
    size_t tid = (size_t)blockIdx.x * blockDim.x + threadIdx.x;
    if (tid < (size_t)(2 * n)) g_cnt[tid] = 0.f;
}

// ---------------------------------------------------------------------------
// K2: edge scatter, one warp per edge; lane l covers floats [4l,4l+4).
// ---------------------------------------------------------------------------
__device__ __forceinline__ void atomic_add_v4(float* p, float4 v)
{
    atomicAdd((float4*)p, v);
}

__global__ void scatter_kernel(const float* __restrict__ x,
                               const void* __restrict__ src_buf,
                               const void* __restrict__ dst_buf,
                               int n, int E)
{
    int warp = (int)(((size_t)blockIdx.x * blockDim.x + threadIdx.x) >> 5);
    int lane = threadIdx.x & 31;
    if (warp >= E) return;

    long long s, d;
    if (g_idx64) {
        const long long* sp = (const long long*)src_buf;
        const long long* dp = dst_buf ? (const long long*)dst_buf : sp + E;
        s = sp[warp]; d = dp[warp];
    } else {
        const int* sp = (const int*)src_buf;
        const int* dp = dst_buf ? (const int*)dst_buf : sp + E;
        s = sp[warp]; d = dp[warp];
    }
    if ((unsigned long long)s >= (unsigned long long)n ||
        (unsigned long long)d >= (unsigned long long)n) return;

    float4 xs = *(const float4*)&x[(size_t)s * IN_DIM + lane * 4];
    float4 xd = *(const float4*)&x[(size_t)d * IN_DIM + lane * 4];

    atomic_add_v4(&g_H[(size_t)d * K_DIM + 128 + lane * 4], xs);
    atomic_add_v4(&g_H[(size_t)s * K_DIM + 256 + lane * 4], xd);

    if (lane == 0) {
        atomicAdd(&g_cnt[d], 1.0f);
        atomicAdd(&g_cnt[n + s], 1.0f);
    }
}

// ---------------------------------------------------------------------------
// K3: normalize aggregate blocks by clamped degree.
// ---------------------------------------------------------------------------
__global__ void normalize_kernel(int n)
{
    const size_t total = (size_t)n * 64;
    for (size_t i = (size_t)blockIdx.x * blockDim.x + threadIdx.x;
         i < total; i += (size_t)gridDim.x * blockDim.x) {
        size_t row = i / 64;
        int    j   = (int)(i % 64);
        float  cnt = (j < 32) ? g_cnt[row] : g_cnt[n + row];
        float  inv = 1.0f / fmaxf(cnt, 1.0f);
        float4* p = (float4*)&g_H[row * K_DIM + 128 + j * 4];
        float4 v = *p;
        v.x *= inv; v.y *= inv; v.z *= inv; v.w *= inv;
        *p = v;
    }
}

// ---------------------------------------------------------------------------
// K4: tensor-core GEMM with bf16 3-term split emulation of fp32.
//   out[M,1024] = relu(g_H[M,384] @ W[384,1024] + b)
// Block: 128x128, BK=32, 256 threads = 8 warps (4x2), warp tile 32x64.
// mma.sync.m16n8k16 bf16 -> f32; per product: hi*hi + hi*lo + lo*hi.
// ---------------------------------------------------------------------------
#define GBM 128
#define GBN 128
#define GBK 32
#define APAD 8
#define BPAD 8

__device__ __forceinline__ uint32_t smem_u32(const void* p)
{
    return (uint32_t)__cvta_generic_to_shared(p);
}

__device__ __forceinline__ void ldsm_x4(uint32_t& r0, uint32_t& r1,
                                        uint32_t& r2, uint32_t& r3, uint32_t addr)
{
    asm volatile("ldmatrix.sync.aligned.m8n8.x4.shared.b16 {%0,%1,%2,%3}, [%4];"
                 : "=r"(r0), "=r"(r1), "=r"(r2), "=r"(r3) : "r"(addr));
}

__device__ __forceinline__ void ldsm_x4_t(uint32_t& r0, uint32_t& r1,
                                          uint32_t& r2, uint32_t& r3, uint32_t addr)
{
    asm volatile("ldmatrix.sync.aligned.m8n8.x4.trans.shared.b16 {%0,%1,%2,%3}, [%4];"
                 : "=r"(r0), "=r"(r1), "=r"(r2), "=r"(r3) : "r"(addr));
}

__device__ __forceinline__ void mma_bf16(float c[4], const uint32_t a[4],
                                         const uint32_t b[2])
{
    asm volatile(
        "mma.sync.aligned.m16n8k16.row.col.f32.bf16.bf16.f32 "
        "{%0,%1,%2,%3}, {%4,%5,%6,%7}, {%8,%9}, {%0,%1,%2,%3};"
        : "+f"(c[0]), "+f"(c[1]), "+f"(c[2]), "+f"(c[3])
        : "r"(a[0]), "r"(a[1]), "r"(a[2]), "r"(a[3]), "r"(b[0]), "r"(b[1]));
}

__global__ __launch_bounds__(256, 1)
void gemm_bf16x3_kernel(const float* __restrict__ W,
                        const float* __restrict__ bias,
                        float* __restrict__ out, int M)
{
    __shared__ __nv_bfloat16 As_hi[GBM][GBK + APAD];
    __shared__ __nv_bfloat16 As_lo[GBM][GBK + APAD];
    __shared__ __nv_bfloat16 Bs_hi[GBK][GBN + BPAD];
    __shared__ __nv_bfloat16 Bs_lo[GBK][GBN + BPAD];

    const int tid  = threadIdx.x;
    const int warp = tid >> 5;
    const int lane = tid & 31;
    const int wm = (warp >> 1) * 32;   // warp M offset within block tile
    const int wn = (warp & 1) * 64;    // warp N offset

    const int rowBase = blockIdx.y * GBM;
    const int colBase = blockIdx.x * GBN;

    float acc[2][8][4];
    #pragma unroll
    for (int i = 0; i < 2; i++)
        #pragma unroll
        for (int j = 0; j < 8; j++)
            #pragma unroll
            for (int c = 0; c < 4; c++) acc[i][j][c] = 0.f;

    // ldmatrix lane addressing
    const int a_row  = lane & 15;          // row within m16
    const int a_koff = (lane >> 4) * 8;    // k chunk 0 / 8
    const int b_k    = lane & 15;          // k row within k16
    const int b_noff = (lane >> 4) * 8;    // n chunk 0 / 8

    for (int k0 = 0; k0 < K_DIM; k0 += GBK) {
        // ---- A tile: 128x32 fp32 -> hi/lo bf16 (Dekker split) ----
        #pragma unroll
        for (int i = 0; i < 4; i++) {
            int linear = tid + i * 256;     // 0..1023 float4s
            int r  = linear >> 3;           // 0..127
            int c4 = linear & 7;            // 0..7
            float4 v = make_float4(0.f, 0.f, 0.f, 0.f);
            int gr = rowBase + r;
            if (gr < M)
                v = *(const float4*)&g_H[(size_t)gr * K_DIM + k0 + c4 * 4];
            float vv[4] = {v.x, v.y, v.z, v.w};
            __nv_bfloat16 h[4], l[4];
            #pragma unroll
            for (int e = 0; e < 4; e++) {
                h[e] = __float2bfloat16(vv[e]);
                l[e] = __float2bfloat16(vv[e] - __bfloat162float(h[e]));
            }
            *(uint2*)&As_hi[r][c4 * 4] = *(uint2*)h;
            *(uint2*)&As_lo[r][c4 * 4] = *(uint2*)l;
        }
        // ---- B tile: 32x128 fp32 -> hi/lo bf16 ----
        #pragma unroll
        for (int i = 0; i < 4; i++) {
            int linear = tid + i * 256;
            int r  = linear >> 5;           // k row 0..31
            int c4 = linear & 31;           // 0..31
            float4 v = *(const float4*)&W[(size_t)(k0 + r) * OUT_DIM + colBase + c4 * 4];
            float vv[4] = {v.x, v.y, v.z, v.w};
            __nv_bfloat16 h[4], l[4];
            #pragma unroll
            for (int e = 0; e < 4; e++) {
                h[e] = __float2bfloat16(vv[e]);
                l[e] = __float2bfloat16(vv[e] - __bfloat162float(h[e]));
            }
            *(uint2*)&Bs_hi[r][c4 * 4] = *(uint2*)h;
            *(uint2*)&Bs_lo[r][c4 * 4] = *(uint2*)l;
        }
        __syncthreads();

        #pragma unroll
        for (int kk = 0; kk < GBK; kk += 16) {
            uint32_t ah[2][4], al[2][4];
            #pragma unroll
            for (int mi = 0; mi < 2; mi++) {
                int row = wm + mi * 16 + a_row;
                ldsm_x4(ah[mi][0], ah[mi][1], ah[mi][2], ah[mi][3],
                        smem_u32(&As_hi[row][kk + a_koff]));
                ldsm_x4(al[mi][0], al[mi][1], al[mi][2], al[mi][3],
                        smem_u32(&As_lo[row][kk + a_koff]));
            }
            uint32_t bh[8][2], bl[8][2];
            #pragma unroll
            for (int nj = 0; nj < 4; nj++) {   // x4.trans loads 2 n8-tiles
                uint32_t r0, r1, r2, r3;
                uint32_t addr = smem_u32(&Bs_hi[kk + b_k][wn + nj * 16 + b_noff]);
                ldsm_x4_t(r0, r1, r2, r3, addr);
                bh[nj*2][0] = r0; bh[nj*2][1] = r1;
                bh[nj*2+1][0] = r2; bh[nj*2+1][1] = r3;
                addr = smem_u32(&Bs_lo[kk + b_k][wn + nj * 16 + b_noff]);
                ldsm_x4_t(r0, r1, r2, r3, addr);
                bl[nj*2][0] = r0; bl[nj*2][1] = r1;
                bl[nj*2+1][0] = r2; bl[nj*2+1][1] = r3;
            }
            #pragma unroll
            for (int mi = 0; mi < 2; mi++)
                #pragma unroll
                for (int nj = 0; nj < 8; nj++) {
                    mma_bf16(acc[mi][nj], ah[mi], bh[nj]);   // hi*hi
                    mma_bf16(acc[mi][nj], ah[mi], bl[nj]);   // hi*lo
                    mma_bf16(acc[mi][nj], al[mi], bh[nj]);   // lo*hi
                }
        }
        __syncthreads();
    }

    // ---- epilogue: +bias, relu, store ----
    const int g = lane >> 2;
    const int t = lane & 3;
    #pragma unroll
    for (int mi = 0; mi < 2; mi++) {
        int r0 = rowBase + wm + mi * 16 + g;
        int r1 = r0 + 8;
        #pragma unroll
        for (int nj = 0; nj < 8; nj++) {
            int c = colBase + wn + nj * 8 + t * 2;
            float2 bv = *(const float2*)&bias[c];
            if (r0 < M) {
                float2 o;
                o.x = fmaxf(acc[mi][nj][0] + bv.x, 0.f);
                o.y = fmaxf(acc[mi][nj][1] + bv.y, 0.f);
                *(float2*)&out[(size_t)r0 * OUT_DIM + c] = o;
            }
            if (r1 < M) {
                float2 o;
                o.x = fmaxf(acc[mi][nj][2] + bv.x, 0.f);
                o.y = fmaxf(acc[mi][nj][3] + bv.y, 0.f);
                *(float2*)&out[(size_t)r1 * OUT_DIM + c] = o;
            }
        }
    }
}

// ---------------------------------------------------------------------------
// launch
// ---------------------------------------------------------------------------
extern "C" void kernel_launch(void* const* d_in, const int* in_sizes, int n_in,
                              void* d_out, int out_size)
{
    const float* x = (const float*)d_in[0];
    const int n = in_sizes[0] / IN_DIM;
    float* out = (float*)d_out;

    const float* W;
    const float* b;
    const void* src_buf;
    const void* dst_buf;
    int E;

    if (n_in >= 5) {
        E = in_sizes[1];
        src_buf = d_in[1];
        dst_buf = d_in[2];
        W = (const float*)d_in[3];
        b = (const float*)d_in[4];
    } else {
        E = in_sizes[1] / 2;
        src_buf = d_in[1];
        dst_buf = nullptr;      // packed: dst derived on device after detect
        W = (const float*)d_in[2];
        b = (const float*)d_in[3];
    }

    detect_kernel<<<1, 1024>>>((const long long*)d_in[1], n, E);
    {
        size_t total = (size_t)n * 96;
        init_kernel<<<(int)((total + 255) / 256), 256>>>(x, n);
    }
    {
        long long threads = (long long)E * 32;
        scatter_kernel<<<(int)((threads + 255) / 256), 256>>>(x, src_buf, dst_buf, n, E);
    }
    {
        size_t total = (size_t)n * 64;
        normalize_kernel<<<(int)((total + 255) / 256), 256>>>(n);
    }
    {
        dim3 grid(OUT_DIM / GBN, (n + GBM - 1) / GBM);
        gemm_bf16x3_kernel<<<grid, 256>>>(W, b, out, n);
    }
}

// round 5
// speedup vs baseline: 2.1202x; 1.2897x over previous
#include <cuda_runtime.h>
#include <cuda_bf16.h>
#include <cstdint>

// ---------------------------------------------------------------------------
// SAGEMean3: out = relu( [x | mean_in | mean_out] @ W + b )
// ---------------------------------------------------------------------------

#define IN_DIM    128
#define K_DIM     384
#define OUT_DIM   1024
#define N_MAX     50000
#define M_PAD     50048          // next multiple of 128

__device__ __align__(16) float g_H[(size_t)N_MAX * 256];     // fp32 aggregates: [:,0:128]=sum_in, [:,128:256]=sum_out
__device__ __align__(16) float g_cnt[2 * N_MAX];
__device__ __align__(16) __nv_bfloat16 g_Ahi[(size_t)M_PAD * K_DIM];
__device__ __align__(16) __nv_bfloat16 g_Alo[(size_t)M_PAD * K_DIM];
__device__ __align__(16) __nv_bfloat16 g_Bhi[(size_t)K_DIM * OUT_DIM];
__device__ __align__(16) __nv_bfloat16 g_Blo[(size_t)K_DIM * OUT_DIM];
__device__ int g_idx64;

// ---------------------------------------------------------------------------
// K0: detect index dtype (parallel).
// ---------------------------------------------------------------------------
__global__ void detect_kernel(const long long* __restrict__ p, int n, int E)
{
    __shared__ int ok;
    if (threadIdx.x == 0) ok = 1;
    __syncthreads();
    int lim = 2 * E < 2048 ? 2 * E : 2048;
    for (int i = threadIdx.x; i < lim; i += blockDim.x) {
        long long v = p[i];
        if (v < 0 || v >= n) ok = 0;
    }
    __syncthreads();
    if (threadIdx.x == 0) g_idx64 = ok;
}

// ---------------------------------------------------------------------------
// K1: zero aggregates, counts, and the GEMM pad rows of g_Ahi/g_Alo.
// ---------------------------------------------------------------------------
__global__ void init_kernel(int n)
{
    const size_t totalH = (size_t)n * 64;      // float4 count for g_H
    size_t tid = (size_t)blockIdx.x * blockDim.x + threadIdx.x;
    for (size_t i = tid; i < totalH; i += (size_t)gridDim.x * blockDim.x)
        *(float4*)&g_H[i * 4] = make_float4(0.f, 0.f, 0.f, 0.f);
    if (tid < (size_t)(2 * n)) g_cnt[tid] = 0.f;
    // pad rows [N_MAX, M_PAD) of A operands: (M_PAD-N_MAX)*384 bf16 = 2304 uint4 each
    const size_t padv = (size_t)(M_PAD - N_MAX) * K_DIM / 8;   // uint4 per array
    if (tid < padv) {
        uint4 z = make_uint4(0, 0, 0, 0);
        *(uint4*)&g_Ahi[(size_t)N_MAX * K_DIM + tid * 8] = z;
        *(uint4*)&g_Alo[(size_t)N_MAX * K_DIM + tid * 8] = z;
    }
}

// ---------------------------------------------------------------------------
// K2: edge scatter, one warp per edge; lane l covers floats [4l,4l+4).
// ---------------------------------------------------------------------------
__global__ void scatter_kernel(const float* __restrict__ x,
                               const void* __restrict__ src_buf,
                               const void* __restrict__ dst_buf,
                               int n, int E)
{
    int warp = (int)(((size_t)blockIdx.x * blockDim.x + threadIdx.x) >> 5);
    int lane = threadIdx.x & 31;
    if (warp >= E) return;

    long long s, d;
    if (g_idx64) {
        const long long* sp = (const long long*)src_buf;
        const long long* dp = dst_buf ? (const long long*)dst_buf : sp + E;
        s = sp[warp]; d = dp[warp];
    } else {
        const int* sp = (const int*)src_buf;
        const int* dp = dst_buf ? (const int*)dst_buf : sp + E;
        s = sp[warp]; d = dp[warp];
    }
    if ((unsigned long long)s >= (unsigned long long)n ||
        (unsigned long long)d >= (unsigned long long)n) return;

    float4 xs = *(const float4*)&x[(size_t)s * IN_DIM + lane * 4];
    float4 xd = *(const float4*)&x[(size_t)d * IN_DIM + lane * 4];

    atomicAdd((float4*)&g_H[(size_t)d * 256 + lane * 4], xs);        // sum_in[dst]
    atomicAdd((float4*)&g_H[(size_t)s * 256 + 128 + lane * 4], xd);  // sum_out[src]

    if (lane == 0) {
        atomicAdd(&g_cnt[d], 1.0f);
        atomicAdd(&g_cnt[n + s], 1.0f);
    }
}

// ---------------------------------------------------------------------------
// K3: build GEMM A operand: [x | mean_in | mean_out] -> bf16 hi/lo split.
// One thread per 4 elements: n*96 tasks.
// ---------------------------------------------------------------------------
__global__ void convert_A_kernel(const float* __restrict__ x, int n)
{
    const size_t total = (size_t)n * 96;
    for (size_t i = (size_t)blockIdx.x * blockDim.x + threadIdx.x;
         i < total; i += (size_t)gridDim.x * blockDim.x) {
        size_t row = i / 96;
        int    c4  = (int)(i % 96);
        float4 v;
        if (c4 < 32) {
            v = *(const float4*)&x[row * IN_DIM + c4 * 4];
        } else {
            int j = c4 - 32;                          // 0..63
            v = *(const float4*)&g_H[row * 256 + j * 4];
            float cnt = (j < 32) ? g_cnt[row] : g_cnt[n + row];
            float inv = 1.0f / fmaxf(cnt, 1.0f);
            v.x *= inv; v.y *= inv; v.z *= inv; v.w *= inv;
        }
        float vv[4] = {v.x, v.y, v.z, v.w};
        __nv_bfloat16 h[4], l[4];
        #pragma unroll
        for (int e = 0; e < 4; e++) {
            h[e] = __float2bfloat16(vv[e]);
            l[e] = __float2bfloat16(vv[e] - __bfloat162float(h[e]));
        }
        *(uint2*)&g_Ahi[row * K_DIM + c4 * 4] = *(uint2*)h;
        *(uint2*)&g_Alo[row * K_DIM + c4 * 4] = *(uint2*)l;
    }
}

// ---------------------------------------------------------------------------
// K3b: W -> bf16 hi/lo (one time per launch; 98304 float4 tasks).
// ---------------------------------------------------------------------------
__global__ void convert_W_kernel(const float* __restrict__ W)
{
    const size_t total = (size_t)K_DIM * OUT_DIM / 4;
    for (size_t i = (size_t)blockIdx.x * blockDim.x + threadIdx.x;
         i < total; i += (size_t)gridDim.x * blockDim.x) {
        float4 v = *(const float4*)&W[i * 4];
        float vv[4] = {v.x, v.y, v.z, v.w};
        __nv_bfloat16 h[4], l[4];
        #pragma unroll
        for (int e = 0; e < 4; e++) {
            h[e] = __float2bfloat16(vv[e]);
            l[e] = __float2bfloat16(vv[e] - __bfloat162float(h[e]));
        }
        *(uint2*)&g_Bhi[i * 4] = *(uint2*)h;
        *(uint2*)&g_Blo[i * 4] = *(uint2*)l;
    }
}

// ---------------------------------------------------------------------------
// K4: pipelined bf16x3 tensor-core GEMM.
// Block 128x128, BK=32, 256 threads (8 warps, 4x2), warp tile 32x64.
// 2-stage cp.async double buffering, operands pre-split in global.
// ---------------------------------------------------------------------------
#define GBM 128
#define GBN 128
#define GBK 32
#define A_STRIDE 40      // bf16 per A smem row (32 + 8 pad)
#define B_STRIDE 136     // bf16 per B smem row (128 + 8 pad)

// dynamic smem layout (bf16 units)
#define AH_OFF(st) ((st) * GBM * A_STRIDE)
#define AL_OFF(st) (2 * GBM * A_STRIDE + (st) * GBM * A_STRIDE)
#define BH_OFF(st) (4 * GBM * A_STRIDE + (st) * GBK * B_STRIDE)
#define BL_OFF(st) (4 * GBM * A_STRIDE + 2 * GBK * B_STRIDE + (st) * GBK * B_STRIDE)
#define SMEM_BF16_TOTAL (4 * GBM * A_STRIDE + 4 * GBK * B_STRIDE)   // 37888

__device__ __forceinline__ uint32_t smem_u32(const void* p)
{
    return (uint32_t)__cvta_generic_to_shared(p);
}

__device__ __forceinline__ void cp16(uint32_t saddr, const void* g)
{
    asm volatile("cp.async.ca.shared.global [%0], [%1], 16;" :: "r"(saddr), "l"(g));
}

__device__ __forceinline__ void ldsm_x4(uint32_t& r0, uint32_t& r1,
                                        uint32_t& r2, uint32_t& r3, uint32_t addr)
{
    asm volatile("ldmatrix.sync.aligned.m8n8.x4.shared.b16 {%0,%1,%2,%3}, [%4];"
                 : "=r"(r0), "=r"(r1), "=r"(r2), "=r"(r3) : "r"(addr));
}

__device__ __forceinline__ void ldsm_x4_t(uint32_t& r0, uint32_t& r1,
                                          uint32_t& r2, uint32_t& r3, uint32_t addr)
{
    asm volatile("ldmatrix.sync.aligned.m8n8.x4.trans.shared.b16 {%0,%1,%2,%3}, [%4];"
                 : "=r"(r0), "=r"(r1), "=r"(r2), "=r"(r3) : "r"(addr));
}

__device__ __forceinline__ void mma_bf16(float c[4], const uint32_t a[4],
                                         const uint32_t b[2])
{
    asm volatile(
        "mma.sync.aligned.m16n8k16.row.col.f32.bf16.bf16.f32 "
        "{%0,%1,%2,%3}, {%4,%5,%6,%7}, {%8,%9}, {%0,%1,%2,%3};"
        : "+f"(c[0]), "+f"(c[1]), "+f"(c[2]), "+f"(c[3])
        : "r"(a[0]), "r"(a[1]), "r"(a[2]), "r"(a[3]), "r"(b[0]), "r"(b[1]));
}

__global__ __launch_bounds__(256, 1)
void gemm_kernel(const float* __restrict__ bias, float* __restrict__ out, int M)
{
    extern __shared__ __nv_bfloat16 smem[];
    const uint32_t sbase = smem_u32(smem);

    const int tid  = threadIdx.x;
    const int warp = tid >> 5;
    const int lane = tid & 31;
    const int wm = (warp >> 1) * 32;
    const int wn = (warp & 1) * 64;

    const int rowBase = blockIdx.y * GBM;   // < M_PAD always (A padded)
    const int colBase = blockIdx.x * GBN;

    float acc[2][8][4];
    #pragma unroll
    for (int i = 0; i < 2; i++)
        #pragma unroll
        for (int j = 0; j < 8; j++)
            #pragma unroll
            for (int c = 0; c < 4; c++) acc[i][j][c] = 0.f;

    auto load_stage = [&](int st, int k0) {
        #pragma unroll
        for (int it = 0; it < 2; it++) {
            int c = tid + it * 256;          // 0..511
            {   // A: 128 rows x 4 chunks of 16B
                int r = c >> 2, o = (c & 3) * 8;
                size_t gofs = (size_t)(rowBase + r) * K_DIM + k0 + o;
                cp16(sbase + (AH_OFF(st) + r * A_STRIDE + o) * 2, &g_Ahi[gofs]);
                cp16(sbase + (AL_OFF(st) + r * A_STRIDE + o) * 2, &g_Alo[gofs]);
            }
            {   // B: 32 rows x 16 chunks of 16B
                int r = c >> 4, o = (c & 15) * 8;
                size_t gofs = (size_t)(k0 + r) * OUT_DIM + colBase + o;
                cp16(sbase + (BH_OFF(st) + r * B_STRIDE + o) * 2, &g_Bhi[gofs]);
                cp16(sbase + (BL_OFF(st) + r * B_STRIDE + o) * 2, &g_Blo[gofs]);
            }
        }
        asm volatile("cp.async.commit_group;");
    };

    const int a_row  = lane & 15;
    const int a_koff = (lane >> 4) * 8;
    const int b_k    = lane & 15;
    const int b_noff = (lane >> 4) * 8;

    load_stage(0, 0);

    const int NITER = K_DIM / GBK;           // 12
    for (int itr = 0; itr < NITER; itr++) {
        if (itr + 1 < NITER) {
            load_stage((itr + 1) & 1, (itr + 1) * GBK);
            asm volatile("cp.async.wait_group 1;");
        } else {
            asm volatile("cp.async.wait_group 0;");
        }
        __syncthreads();

        const int st = itr & 1;
        const __nv_bfloat16* Ah = smem + AH_OFF(st);
        const __nv_bfloat16* Al = smem + AL_OFF(st);
        const __nv_bfloat16* Bh = smem + BH_OFF(st);
        const __nv_bfloat16* Bl = smem + BL_OFF(st);

        #pragma unroll
        for (int kk = 0; kk < GBK; kk += 16) {
            uint32_t ah[2][4], al[2][4];
            #pragma unroll
            for (int mi = 0; mi < 2; mi++) {
                int row = wm + mi * 16 + a_row;
                ldsm_x4(ah[mi][0], ah[mi][1], ah[mi][2], ah[mi][3],
                        smem_u32(Ah + row * A_STRIDE + kk + a_koff));
                ldsm_x4(al[mi][0], al[mi][1], al[mi][2], al[mi][3],
                        smem_u32(Al + row * A_STRIDE + kk + a_koff));
            }
            uint32_t bh[8][2], bl[8][2];
            #pragma unroll
            for (int nj = 0; nj < 4; nj++) {
                uint32_t r0, r1, r2, r3;
                ldsm_x4_t(r0, r1, r2, r3,
                          smem_u32(Bh + (kk + b_k) * B_STRIDE + wn + nj * 16 + b_noff));
                bh[nj*2][0] = r0; bh[nj*2][1] = r1;
                bh[nj*2+1][0] = r2; bh[nj*2+1][1] = r3;
                ldsm_x4_t(r0, r1, r2, r3,
                          smem_u32(Bl + (kk + b_k) * B_STRIDE + wn + nj * 16 + b_noff));
                bl[nj*2][0] = r0; bl[nj*2][1] = r1;
                bl[nj*2+1][0] = r2; bl[nj*2+1][1] = r3;
            }
            #pragma unroll
            for (int mi = 0; mi < 2; mi++)
                #pragma unroll
                for (int nj = 0; nj < 8; nj++) {
                    mma_bf16(acc[mi][nj], ah[mi], bh[nj]);
                    mma_bf16(acc[mi][nj], ah[mi], bl[nj]);
                    mma_bf16(acc[mi][nj], al[mi], bh[nj]);
                }
        }
        __syncthreads();
    }

    // epilogue
    const int g = lane >> 2;
    const int t = lane & 3;
    #pragma unroll
    for (int mi = 0; mi < 2; mi++) {
        int r0 = rowBase + wm + mi * 16 + g;
        int r1 = r0 + 8;
        #pragma unroll
        for (int nj = 0; nj < 8; nj++) {
            int c = colBase + wn + nj * 8 + t * 2;
            float2 bv = *(const float2*)&bias[c];
            if (r0 < M) {
                float2 o;
                o.x = fmaxf(acc[mi][nj][0] + bv.x, 0.f);
                o.y = fmaxf(acc[mi][nj][1] + bv.y, 0.f);
                *(float2*)&out[(size_t)r0 * OUT_DIM + c] = o;
            }
            if (r1 < M) {
                float2 o;
                o.x = fmaxf(acc[mi][nj][2] + bv.x, 0.f);
                o.y = fmaxf(acc[mi][nj][3] + bv.y, 0.f);
                *(float2*)&out[(size_t)r1 * OUT_DIM + c] = o;
            }
        }
    }
}

// ---------------------------------------------------------------------------
// launch
// ---------------------------------------------------------------------------
extern "C" void kernel_launch(void* const* d_in, const int* in_sizes, int n_in,
                              void* d_out, int out_size)
{
    const float* x = (const float*)d_in[0];
    const int n = in_sizes[0] / IN_DIM;
    float* out = (float*)d_out;

    const float* W;
    const float* b;
    const void* src_buf;
    const void* dst_buf;
    int E;

    if (n_in >= 5) {
        E = in_sizes[1];
        src_buf = d_in[1];
        dst_buf = d_in[2];
        W = (const float*)d_in[3];
        b = (const float*)d_in[4];
    } else {
        E = in_sizes[1] / 2;
        src_buf = d_in[1];
        dst_buf = nullptr;
        W = (const float*)d_in[2];
        b = (const float*)d_in[3];
    }

    detect_kernel<<<1, 1024>>>((const long long*)d_in[1], n, E);
    {
        size_t total = (size_t)n * 64;
        init_kernel<<<(int)((total + 255) / 256), 256>>>(n);
    }
    {
        long long threads = (long long)E * 32;
        scatter_kernel<<<(int)((threads + 255) / 256), 256>>>(x, src_buf, dst_buf, n, E);
    }
    {
        size_t total = (size_t)n * 96;
        convert_A_kernel<<<(int)((total + 255) / 256), 256>>>(x, n);
    }
    convert_W_kernel<<<384, 256>>>(W);
    {
        static const int smem_bytes = SMEM_BF16_TOTAL * 2;   // 75776
        cudaFuncSetAttribute(gemm_kernel,
                             cudaFuncAttributeMaxDynamicSharedMemorySize, smem_bytes);
        dim3 grid(OUT_DIM / GBN, M_PAD / GBM);
        gemm_kernel<<<grid, 256, smem_bytes>>>(b, out, n);
    }
}

// round 6
// speedup vs baseline: 2.3801x; 1.1226x over previous
#include <cuda_runtime.h>
#include <cuda_bf16.h>
#include <cstdint>

// ---------------------------------------------------------------------------
// SAGEMean3: out = relu( [x | mean_in | mean_out] @ W + b )
// CSR-gather aggregation (no feature atomics) + bf16x3 tensor-core GEMM.
// ---------------------------------------------------------------------------

#define IN_DIM    128
#define K_DIM     384
#define OUT_DIM   1024
#define N_MAX     50000
#define M_PAD     50048          // next multiple of 128
#define E_MAX     700000

__device__ __align__(16) __nv_bfloat16 g_Ahi[(size_t)M_PAD * K_DIM];
__device__ __align__(16) __nv_bfloat16 g_Alo[(size_t)M_PAD * K_DIM];
__device__ __align__(16) __nv_bfloat16 g_Bhi[(size_t)K_DIM * OUT_DIM];
__device__ __align__(16) __nv_bfloat16 g_Blo[(size_t)K_DIM * OUT_DIM];
__device__ int g_deg[2 * N_MAX];          // [0:n) in-deg(dst), [n:2n) out-deg(src)
__device__ int g_off[2 * N_MAX + 1];      // CSR offsets (both directions concatenated)
__device__ int g_cur[2 * N_MAX];          // fill cursors
__device__ int g_adj[2 * E_MAX];          // adjacency (in-neighbors then out-neighbors segments)
__device__ int g_bsum[256];               // scan block sums
__device__ int g_bscan[256];              // scanned block sums
__device__ int g_idx64;

#define SCAN_BS 512

// ---------------------------------------------------------------------------
// K0: detect index dtype (int64 vs int32) on device.
// ---------------------------------------------------------------------------
__global__ void detect_kernel(const long long* __restrict__ p, int n, int E)
{
    __shared__ int ok;
    if (threadIdx.x == 0) ok = 1;
    __syncthreads();
    int lim = 2 * E < 2048 ? 2 * E : 2048;
    for (int i = threadIdx.x; i < lim; i += blockDim.x) {
        long long v = p[i];
        if (v < 0 || v >= n) ok = 0;
    }
    __syncthreads();
    if (threadIdx.x == 0) g_idx64 = ok;
}

// ---------------------------------------------------------------------------
// edge decode helper (packed layout => dst at +E elements of detected dtype)
// ---------------------------------------------------------------------------
__device__ __forceinline__ void load_edge(const void* src_buf, const void* dst_buf,
                                          int e, int E, long long& s, long long& d)
{
    if (g_idx64) {
        const long long* sp = (const long long*)src_buf;
        const long long* dp = dst_buf ? (const long long*)dst_buf : sp + E;
        s = sp[e]; d = dp[e];
    } else {
        const int* sp = (const int*)src_buf;
        const int* dp = dst_buf ? (const int*)dst_buf : sp + E;
        s = sp[e]; d = dp[e];
    }
}

// ---------------------------------------------------------------------------
// K1: zero degrees + zero GEMM pad rows of A operands.
// ---------------------------------------------------------------------------
__global__ void zero_kernel(int n)
{
    size_t tid = (size_t)blockIdx.x * blockDim.x + threadIdx.x;
    if (tid < (size_t)(2 * n)) g_deg[tid] = 0;
    const size_t padv = (size_t)(M_PAD - N_MAX) * K_DIM / 8;
    if (tid < padv) {
        uint4 z = make_uint4(0, 0, 0, 0);
        *(uint4*)&g_Ahi[(size_t)N_MAX * K_DIM + tid * 8] = z;
        *(uint4*)&g_Alo[(size_t)N_MAX * K_DIM + tid * 8] = z;
    }
}

// ---------------------------------------------------------------------------
// K2: degree histogram.
// ---------------------------------------------------------------------------
__global__ void hist_kernel(const void* __restrict__ src_buf,
                            const void* __restrict__ dst_buf, int n, int E)
{
    int e = blockIdx.x * blockDim.x + threadIdx.x;
    if (e >= E) return;
    long long s, d;
    load_edge(src_buf, dst_buf, e, E, s, d);
    if ((unsigned long long)s >= (unsigned long long)n ||
        (unsigned long long)d >= (unsigned long long)n) return;
    atomicAdd(&g_deg[d], 1);          // in-degree
    atomicAdd(&g_deg[n + (int)s], 1); // out-degree
}

// ---------------------------------------------------------------------------
// K3a/b/c: exclusive scan of g_deg[0..2n) into g_off.
// ---------------------------------------------------------------------------
__global__ void scan1_kernel(int total)
{
    __shared__ int sh[SCAN_BS];
    int i = blockIdx.x * SCAN_BS + threadIdx.x;
    int v = (i < total) ? g_deg[i] : 0;
    sh[threadIdx.x] = v;
    __syncthreads();
    #pragma unroll
    for (int off = 1; off < SCAN_BS; off <<= 1) {
        int t = (threadIdx.x >= off) ? sh[threadIdx.x - off] : 0;
        __syncthreads();
        sh[threadIdx.x] += t;
        __syncthreads();
    }
    if (i < total) g_off[i] = sh[threadIdx.x] - v;   // exclusive
    if (threadIdx.x == SCAN_BS - 1) g_bsum[blockIdx.x] = sh[SCAN_BS - 1];
}

__global__ void scan2_kernel(int nblocks)
{
    __shared__ int sh[256];
    int v = (threadIdx.x < nblocks) ? g_bsum[threadIdx.x] : 0;
    sh[threadIdx.x] = v;
    __syncthreads();
    #pragma unroll
    for (int off = 1; off < 256; off <<= 1) {
        int t = (threadIdx.x >= off) ? sh[threadIdx.x - off] : 0;
        __syncthreads();
        sh[threadIdx.x] += t;
        __syncthreads();
    }
    if (threadIdx.x < nblocks) g_bscan[threadIdx.x] = sh[threadIdx.x] - v;
}

__global__ void scan3_kernel(int total, int grand_total)
{
    int i = blockIdx.x * SCAN_BS + threadIdx.x;
    if (i < total) {
        int o = g_off[i] + g_bscan[blockIdx.x];
        g_off[i] = o;
        g_cur[i] = o;
    }
    if (i == 0) g_off[total] = grand_total;
}

// ---------------------------------------------------------------------------
// K4: fill adjacency.
// ---------------------------------------------------------------------------
__global__ void fill_kernel(const void* __restrict__ src_buf,
                            const void* __restrict__ dst_buf, int n, int E)
{
    int e = blockIdx.x * blockDim.x + threadIdx.x;
    if (e >= E) return;
    long long s, d;
    load_edge(src_buf, dst_buf, e, E, s, d);
    if ((unsigned long long)s >= (unsigned long long)n ||
        (unsigned long long)d >= (unsigned long long)n) return;
    int p0 = atomicAdd(&g_cur[d], 1);
    g_adj[p0] = (int)s;                       // in-neighbor of dst
    int p1 = atomicAdd(&g_cur[n + (int)s], 1);
    g_adj[p1] = (int)d;                       // out-neighbor of src
}

// ---------------------------------------------------------------------------
// K5: gather means. One warp per (node, direction); lane l covers floats
// [4l,4l+4). Writes bf16 hi/lo mean directly into A operand cols 128..383.
// ---------------------------------------------------------------------------
__global__ void gather_kernel(const float* __restrict__ x, int n)
{
    int seg  = (int)(((size_t)blockIdx.x * blockDim.x + threadIdx.x) >> 5);
    int lane = threadIdx.x & 31;
    if (seg >= 2 * n) return;

    int start = g_off[seg];
    int end   = g_off[seg + 1];

    float4 acc = make_float4(0.f, 0.f, 0.f, 0.f);
    for (int base = start; base < end; base += 32) {
        int m = end - base;
        int idx = (base + lane < end) ? g_adj[base + lane] : 0;
        if (m >= 32) {
            #pragma unroll
            for (int j = 0; j < 32; j++) {
                int nb = __shfl_sync(0xffffffffu, idx, j);
                float4 v = *(const float4*)&x[(size_t)nb * IN_DIM + lane * 4];
                acc.x += v.x; acc.y += v.y; acc.z += v.z; acc.w += v.w;
            }
        } else {
            for (int j = 0; j < m; j++) {
                int nb = __shfl_sync(0xffffffffu, idx, j);
                float4 v = *(const float4*)&x[(size_t)nb * IN_DIM + lane * 4];
                acc.x += v.x; acc.y += v.y; acc.z += v.z; acc.w += v.w;
            }
        }
    }

    float inv = 1.0f / fmaxf((float)(end - start), 1.0f);
    float vv[4] = {acc.x * inv, acc.y * inv, acc.z * inv, acc.w * inv};

    int node = (seg < n) ? seg : seg - n;
    int col  = ((seg < n) ? 128 : 256) + lane * 4;

    __nv_bfloat16 h[4], l[4];
    #pragma unroll
    for (int e = 0; e < 4; e++) {
        h[e] = __float2bfloat16(vv[e]);
        l[e] = __float2bfloat16(vv[e] - __bfloat162float(h[e]));
    }
    *(uint2*)&g_Ahi[(size_t)node * K_DIM + col] = *(uint2*)h;
    *(uint2*)&g_Alo[(size_t)node * K_DIM + col] = *(uint2*)l;
}

// ---------------------------------------------------------------------------
// K6: x -> bf16 hi/lo into A operand cols 0..127.
// ---------------------------------------------------------------------------
__global__ void convert_x_kernel(const float* __restrict__ x, int n)
{
    const size_t total = (size_t)n * 32;
    for (size_t i = (size_t)blockIdx.x * blockDim.x + threadIdx.x;
         i < total; i += (size_t)gridDim.x * blockDim.x) {
        size_t row = i >> 5;
        int    c4  = (int)(i & 31);
        float4 v = *(const float4*)&x[row * IN_DIM + c4 * 4];
        float vv[4] = {v.x, v.y, v.z, v.w};
        __nv_bfloat16 h[4], l[4];
        #pragma unroll
        for (int e = 0; e < 4; e++) {
            h[e] = __float2bfloat16(vv[e]);
            l[e] = __float2bfloat16(vv[e] - __bfloat162float(h[e]));
        }
        *(uint2*)&g_Ahi[row * K_DIM + c4 * 4] = *(uint2*)h;
        *(uint2*)&g_Alo[row * K_DIM + c4 * 4] = *(uint2*)l;
    }
}

// ---------------------------------------------------------------------------
// K7: W -> bf16 hi/lo.
// ---------------------------------------------------------------------------
__global__ void convert_W_kernel(const float* __restrict__ W)
{
    const size_t total = (size_t)K_DIM * OUT_DIM / 4;
    for (size_t i = (size_t)blockIdx.x * blockDim.x + threadIdx.x;
         i < total; i += (size_t)gridDim.x * blockDim.x) {
        float4 v = *(const float4*)&W[i * 4];
        float vv[4] = {v.x, v.y, v.z, v.w};
        __nv_bfloat16 h[4], l[4];
        #pragma unroll
        for (int e = 0; e < 4; e++) {
            h[e] = __float2bfloat16(vv[e]);
            l[e] = __float2bfloat16(vv[e] - __bfloat162float(h[e]));
        }
        *(uint2*)&g_Bhi[i * 4] = *(uint2*)h;
        *(uint2*)&g_Blo[i * 4] = *(uint2*)l;
    }
}

// ---------------------------------------------------------------------------
// K8: pipelined bf16x3 tensor-core GEMM (unchanged from R5).
// ---------------------------------------------------------------------------
#define GBM 128
#define GBN 128
#define GBK 32
#define A_STRIDE 40
#define B_STRIDE 136

#define AH_OFF(st) ((st) * GBM * A_STRIDE)
#define AL_OFF(st) (2 * GBM * A_STRIDE + (st) * GBM * A_STRIDE)
#define BH_OFF(st) (4 * GBM * A_STRIDE + (st) * GBK * B_STRIDE)
#define BL_OFF(st) (4 * GBM * A_STRIDE + 2 * GBK * B_STRIDE + (st) * GBK * B_STRIDE)
#define SMEM_BF16_TOTAL (4 * GBM * A_STRIDE + 4 * GBK * B_STRIDE)

__device__ __forceinline__ uint32_t smem_u32(const void* p)
{
    return (uint32_t)__cvta_generic_to_shared(p);
}

__device__ __forceinline__ void cp16(uint32_t saddr, const void* g)
{
    asm volatile("cp.async.ca.shared.global [%0], [%1], 16;" :: "r"(saddr), "l"(g));
}

__device__ __forceinline__ void ldsm_x4(uint32_t& r0, uint32_t& r1,
                                        uint32_t& r2, uint32_t& r3, uint32_t addr)
{
    asm volatile("ldmatrix.sync.aligned.m8n8.x4.shared.b16 {%0,%1,%2,%3}, [%4];"
                 : "=r"(r0), "=r"(r1), "=r"(r2), "=r"(r3) : "r"(addr));
}

__device__ __forceinline__ void ldsm_x4_t(uint32_t& r0, uint32_t& r1,
                                          uint32_t& r2, uint32_t& r3, uint32_t addr)
{
    asm volatile("ldmatrix.sync.aligned.m8n8.x4.trans.shared.b16 {%0,%1,%2,%3}, [%4];"
                 : "=r"(r0), "=r"(r1), "=r"(r2), "=r"(r3) : "r"(addr));
}

__device__ __forceinline__ void mma_bf16(float c[4], const uint32_t a[4],
                                         const uint32_t b[2])
{
    asm volatile(
        "mma.sync.aligned.m16n8k16.row.col.f32.bf16.bf16.f32 "
        "{%0,%1,%2,%3}, {%4,%5,%6,%7}, {%8,%9}, {%0,%1,%2,%3};"
        : "+f"(c[0]), "+f"(c[1]), "+f"(c[2]), "+f"(c[3])
        : "r"(a[0]), "r"(a[1]), "r"(a[2]), "r"(a[3]), "r"(b[0]), "r"(b[1]));
}

__global__ __launch_bounds__(256, 1)
void gemm_kernel(const float* __restrict__ bias, float* __restrict__ out, int M)
{
    extern __shared__ __nv_bfloat16 smem[];
    const uint32_t sbase = smem_u32(smem);

    const int tid  = threadIdx.x;
    const int warp = tid >> 5;
    const int lane = tid & 31;
    const int wm = (warp >> 1) * 32;
    const int wn = (warp & 1) * 64;

    const int rowBase = blockIdx.y * GBM;
    const int colBase = blockIdx.x * GBN;

    float acc[2][8][4];
    #pragma unroll
    for (int i = 0; i < 2; i++)
        #pragma unroll
        for (int j = 0; j < 8; j++)
            #pragma unroll
            for (int c = 0; c < 4; c++) acc[i][j][c] = 0.f;

    auto load_stage = [&](int st, int k0) {
        #pragma unroll
        for (int it = 0; it < 2; it++) {
            int c = tid + it * 256;
            {
                int r = c >> 2, o = (c & 3) * 8;
                size_t gofs = (size_t)(rowBase + r) * K_DIM + k0 + o;
                cp16(sbase + (AH_OFF(st) + r * A_STRIDE + o) * 2, &g_Ahi[gofs]);
                cp16(sbase + (AL_OFF(st) + r * A_STRIDE + o) * 2, &g_Alo[gofs]);
            }
            {
                int r = c >> 4, o = (c & 15) * 8;
                size_t gofs = (size_t)(k0 + r) * OUT_DIM + colBase + o;
                cp16(sbase + (BH_OFF(st) + r * B_STRIDE + o) * 2, &g_Bhi[gofs]);
                cp16(sbase + (BL_OFF(st) + r * B_STRIDE + o) * 2, &g_Blo[gofs]);
            }
        }
        asm volatile("cp.async.commit_group;");
    };

    const int a_row  = lane & 15;
    const int a_koff = (lane >> 4) * 8;
    const int b_k    = lane & 15;
    const int b_noff = (lane >> 4) * 8;

    load_stage(0, 0);

    const int NITER = K_DIM / GBK;
    for (int itr = 0; itr < NITER; itr++) {
        if (itr + 1 < NITER) {
            load_stage((itr + 1) & 1, (itr + 1) * GBK);
            asm volatile("cp.async.wait_group 1;");
        } else {
            asm volatile("cp.async.wait_group 0;");
        }
        __syncthreads();

        const int st = itr & 1;
        const __nv_bfloat16* Ah = smem + AH_OFF(st);
        const __nv_bfloat16* Al = smem + AL_OFF(st);
        const __nv_bfloat16* Bh = smem + BH_OFF(st);
        const __nv_bfloat16* Bl = smem + BL_OFF(st);

        #pragma unroll
        for (int kk = 0; kk < GBK; kk += 16) {
            uint32_t ah[2][4], al[2][4];
            #pragma unroll
            for (int mi = 0; mi < 2; mi++) {
                int row = wm + mi * 16 + a_row;
                ldsm_x4(ah[mi][0], ah[mi][1], ah[mi][2], ah[mi][3],
                        smem_u32(Ah + row * A_STRIDE + kk + a_koff));
                ldsm_x4(al[mi][0], al[mi][1], al[mi][2], al[mi][3],
                        smem_u32(Al + row * A_STRIDE + kk + a_koff));
            }
            uint32_t bh[8][2], bl[8][2];
            #pragma unroll
            for (int nj = 0; nj < 4; nj++) {
                uint32_t r0, r1, r2, r3;
                ldsm_x4_t(r0, r1, r2, r3,
                          smem_u32(Bh + (kk + b_k) * B_STRIDE + wn + nj * 16 + b_noff));
                bh[nj*2][0] = r0; bh[nj*2][1] = r1;
                bh[nj*2+1][0] = r2; bh[nj*2+1][1] = r3;
                ldsm_x4_t(r0, r1, r2, r3,
                          smem_u32(Bl + (kk + b_k) * B_STRIDE + wn + nj * 16 + b_noff));
                bl[nj*2][0] = r0; bl[nj*2][1] = r1;
                bl[nj*2+1][0] = r2; bl[nj*2+1][1] = r3;
            }
            #pragma unroll
            for (int mi = 0; mi < 2; mi++)
                #pragma unroll
                for (int nj = 0; nj < 8; nj++) {
                    mma_bf16(acc[mi][nj], ah[mi], bh[nj]);
                    mma_bf16(acc[mi][nj], ah[mi], bl[nj]);
                    mma_bf16(acc[mi][nj], al[mi], bh[nj]);
                }
        }
        __syncthreads();
    }

    const int g = lane >> 2;
    const int t = lane & 3;
    #pragma unroll
    for (int mi = 0; mi < 2; mi++) {
        int r0 = rowBase + wm + mi * 16 + g;
        int r1 = r0 + 8;
        #pragma unroll
        for (int nj = 0; nj < 8; nj++) {
            int c = colBase + wn + nj * 8 + t * 2;
            float2 bv = *(const float2*)&bias[c];
            if (r0 < M) {
                float2 o;
                o.x = fmaxf(acc[mi][nj][0] + bv.x, 0.f);
                o.y = fmaxf(acc[mi][nj][1] + bv.y, 0.f);
                *(float2*)&out[(size_t)r0 * OUT_DIM + c] = o;
            }
            if (r1 < M) {
                float2 o;
                o.x = fmaxf(acc[mi][nj][2] + bv.x, 0.f);
                o.y = fmaxf(acc[mi][nj][3] + bv.y, 0.f);
                *(float2*)&out[(size_t)r1 * OUT_DIM + c] = o;
            }
        }
    }
}

// ---------------------------------------------------------------------------
// launch
// ---------------------------------------------------------------------------
extern "C" void kernel_launch(void* const* d_in, const int* in_sizes, int n_in,
                              void* d_out, int out_size)
{
    const float* x = (const float*)d_in[0];
    const int n = in_sizes[0] / IN_DIM;
    float* out = (float*)d_out;

    const float* W;
    const float* b;
    const void* src_buf;
    const void* dst_buf;
    int E;

    if (n_in >= 5) {
        E = in_sizes[1];
        src_buf = d_in[1];
        dst_buf = d_in[2];
        W = (const float*)d_in[3];
        b = (const float*)d_in[4];
    } else {
        E = in_sizes[1] / 2;
        src_buf = d_in[1];
        dst_buf = nullptr;
        W = (const float*)d_in[2];
        b = (const float*)d_in[3];
    }

    const int total = 2 * n;                                  // segment count
    const int scan_blocks = (total + SCAN_BS - 1) / SCAN_BS;  // 196

    detect_kernel<<<1, 1024>>>((const long long*)d_in[1], n, E);
    {
        size_t work = (size_t)(M_PAD - N_MAX) * K_DIM / 8;
        if ((size_t)total > work) work = total;
        zero_kernel<<<(int)((work + 255) / 256), 256>>>(n);
    }
    hist_kernel<<<(E + 255) / 256, 256>>>(src_buf, dst_buf, n, E);
    scan1_kernel<<<scan_blocks, SCAN_BS>>>(total);
    scan2_kernel<<<1, 256>>>(scan_blocks);
    scan3_kernel<<<scan_blocks, SCAN_BS>>>(total, 2 * E);
    fill_kernel<<<(E + 255) / 256, 256>>>(src_buf, dst_buf, n, E);
    {
        long long threads = (long long)total * 32;
        gather_kernel<<<(int)((threads + 255) / 256), 256>>>(x, n);
    }
    {
        size_t t2 = (size_t)n * 32;
        convert_x_kernel<<<(int)((t2 + 255) / 256), 256>>>(x, n);
    }
    convert_W_kernel<<<384, 256>>>(W);
    {
        static const int smem_bytes = SMEM_BF16_TOTAL * 2;
        cudaFuncSetAttribute(gemm_kernel,
                             cudaFuncAttributeMaxDynamicSharedMemorySize, smem_bytes);
        dim3 grid(OUT_DIM / GBN, M_PAD / GBM);
        gemm_kernel<<<grid, 256, smem_bytes>>>(b, out, n);
    }
}

// round 7
// speedup vs baseline: 2.4901x; 1.0462x over previous
#include <cuda_runtime.h>
#include <cuda_bf16.h>
#include <cstdint>

// ---------------------------------------------------------------------------
// SAGEMean3: out = relu( [x | mean_in | mean_out] @ W + b )
// CSR-gather aggregation + bf16x3 tensor-core GEMM (128x256 tiles).
// ---------------------------------------------------------------------------

#define IN_DIM    128
#define K_DIM     384
#define OUT_DIM   1024
#define N_MAX     50000
#define M_PAD     50048          // multiple of 128
#define E_MAX     700000

__device__ __align__(16) __nv_bfloat16 g_Ahi[(size_t)M_PAD * K_DIM];
__device__ __align__(16) __nv_bfloat16 g_Alo[(size_t)M_PAD * K_DIM];
__device__ __align__(16) __nv_bfloat16 g_Bhi[(size_t)K_DIM * OUT_DIM];
__device__ __align__(16) __nv_bfloat16 g_Blo[(size_t)K_DIM * OUT_DIM];
__device__ int g_deg[2 * N_MAX];
__device__ int g_off[2 * N_MAX + 1];
__device__ int g_cur[2 * N_MAX];
__device__ int g_adj[2 * E_MAX];
__device__ int g_bsum[256];
__device__ int g_bscan[256];
__device__ int g_idx64;

#define SCAN_BS 512

// ---------------------------------------------------------------------------
// K1: (block 0) detect index dtype + zero degrees + zero GEMM pad rows.
// ---------------------------------------------------------------------------
__global__ void zero_detect_kernel(const long long* __restrict__ ei, int n, int E)
{
    if (blockIdx.x == 0) {
        __shared__ int ok;
        if (threadIdx.x == 0) ok = 1;
        __syncthreads();
        int lim = 2 * E < 2048 ? 2 * E : 2048;
        for (int i = threadIdx.x; i < lim; i += blockDim.x) {
            long long v = ei[i];
            if (v < 0 || v >= n) ok = 0;
        }
        __syncthreads();
        if (threadIdx.x == 0) g_idx64 = ok;
    }
    size_t tid = (size_t)blockIdx.x * blockDim.x + threadIdx.x;
    if (tid < (size_t)(2 * n)) g_deg[tid] = 0;
    const size_t padv = (size_t)(M_PAD - N_MAX) * K_DIM / 8;
    if (tid < padv) {
        uint4 z = make_uint4(0, 0, 0, 0);
        *(uint4*)&g_Ahi[(size_t)N_MAX * K_DIM + tid * 8] = z;
        *(uint4*)&g_Alo[(size_t)N_MAX * K_DIM + tid * 8] = z;
    }
}

// ---------------------------------------------------------------------------
// edge decode helper (packed layout => dst at +E elements of detected dtype)
// ---------------------------------------------------------------------------
__device__ __forceinline__ void load_edge(const void* src_buf, const void* dst_buf,
                                          int e, int E, long long& s, long long& d)
{
    if (g_idx64) {
        const long long* sp = (const long long*)src_buf;
        const long long* dp = dst_buf ? (const long long*)dst_buf : sp + E;
        s = sp[e]; d = dp[e];
    } else {
        const int* sp = (const int*)src_buf;
        const int* dp = dst_buf ? (const int*)dst_buf : sp + E;
        s = sp[e]; d = dp[e];
    }
}

// ---------------------------------------------------------------------------
// K2: degree histogram.
// ---------------------------------------------------------------------------
__global__ void hist_kernel(const void* __restrict__ src_buf,
                            const void* __restrict__ dst_buf, int n, int E)
{
    int e = blockIdx.x * blockDim.x + threadIdx.x;
    if (e >= E) return;
    long long s, d;
    load_edge(src_buf, dst_buf, e, E, s, d);
    if ((unsigned long long)s >= (unsigned long long)n ||
        (unsigned long long)d >= (unsigned long long)n) return;
    atomicAdd(&g_deg[d], 1);
    atomicAdd(&g_deg[n + (int)s], 1);
}

// ---------------------------------------------------------------------------
// K3a/b/c: exclusive scan of g_deg into g_off.
// ---------------------------------------------------------------------------
__global__ void scan1_kernel(int total)
{
    __shared__ int sh[SCAN_BS];
    int i = blockIdx.x * SCAN_BS + threadIdx.x;
    int v = (i < total) ? g_deg[i] : 0;
    sh[threadIdx.x] = v;
    __syncthreads();
    #pragma unroll
    for (int off = 1; off < SCAN_BS; off <<= 1) {
        int t = (threadIdx.x >= off) ? sh[threadIdx.x - off] : 0;
        __syncthreads();
        sh[threadIdx.x] += t;
        __syncthreads();
    }
    if (i < total) g_off[i] = sh[threadIdx.x] - v;
    if (threadIdx.x == SCAN_BS - 1) g_bsum[blockIdx.x] = sh[SCAN_BS - 1];
}

__global__ void scan2_kernel(int nblocks)
{
    __shared__ int sh[256];
    int v = (threadIdx.x < nblocks) ? g_bsum[threadIdx.x] : 0;
    sh[threadIdx.x] = v;
    __syncthreads();
    #pragma unroll
    for (int off = 1; off < 256; off <<= 1) {
        int t = (threadIdx.x >= off) ? sh[threadIdx.x - off] : 0;
        __syncthreads();
        sh[threadIdx.x] += t;
        __syncthreads();
    }
    if (threadIdx.x < nblocks) g_bscan[threadIdx.x] = sh[threadIdx.x] - v;
}

__global__ void scan3_kernel(int total, int grand_total)
{
    int i = blockIdx.x * SCAN_BS + threadIdx.x;
    if (i < total) {
        int o = g_off[i] + g_bscan[blockIdx.x];
        g_off[i] = o;
        g_cur[i] = o;
    }
    if (i == 0) g_off[total] = grand_total;
}

// ---------------------------------------------------------------------------
// K4: fill adjacency.
// ---------------------------------------------------------------------------
__global__ void fill_kernel(const void* __restrict__ src_buf,
                            const void* __restrict__ dst_buf, int n, int E)
{
    int e = blockIdx.x * blockDim.x + threadIdx.x;
    if (e >= E) return;
    long long s, d;
    load_edge(src_buf, dst_buf, e, E, s, d);
    if ((unsigned long long)s >= (unsigned long long)n ||
        (unsigned long long)d >= (unsigned long long)n) return;
    int p0 = atomicAdd(&g_cur[d], 1);
    g_adj[p0] = (int)s;
    int p1 = atomicAdd(&g_cur[n + (int)s], 1);
    g_adj[p1] = (int)d;
}

// ---------------------------------------------------------------------------
// K5: gather means + (for in-direction warps) convert own x row.
// One warp per (node, direction); lane l covers floats [4l,4l+4).
// ---------------------------------------------------------------------------
__device__ __forceinline__ void split_store(size_t ofs, const float vv[4])
{
    __nv_bfloat16 h[4], l[4];
    #pragma unroll
    for (int e = 0; e < 4; e++) {
        h[e] = __float2bfloat16(vv[e]);
        l[e] = __float2bfloat16(vv[e] - __bfloat162float(h[e]));
    }
    *(uint2*)&g_Ahi[ofs] = *(uint2*)h;
    *(uint2*)&g_Alo[ofs] = *(uint2*)l;
}

__global__ void gather_kernel(const float* __restrict__ x, int n)
{
    int seg  = (int)(((size_t)blockIdx.x * blockDim.x + threadIdx.x) >> 5);
    int lane = threadIdx.x & 31;
    if (seg >= 2 * n) return;

    int start = g_off[seg];
    int end   = g_off[seg + 1];
    int node  = (seg < n) ? seg : seg - n;

    float4 acc = make_float4(0.f, 0.f, 0.f, 0.f);
    for (int base = start; base < end; base += 32) {
        int m = end - base;
        int idx = (base + lane < end) ? g_adj[base + lane] : 0;
        if (m >= 32) {
            #pragma unroll
            for (int j = 0; j < 32; j++) {
                int nb = __shfl_sync(0xffffffffu, idx, j);
                float4 v = *(const float4*)&x[(size_t)nb * IN_DIM + lane * 4];
                acc.x += v.x; acc.y += v.y; acc.z += v.z; acc.w += v.w;
            }
        } else {
            for (int j = 0; j < m; j++) {
                int nb = __shfl_sync(0xffffffffu, idx, j);
                float4 v = *(const float4*)&x[(size_t)nb * IN_DIM + lane * 4];
                acc.x += v.x; acc.y += v.y; acc.z += v.z; acc.w += v.w;
            }
        }
    }

    float inv = 1.0f / fmaxf((float)(end - start), 1.0f);
    float vv[4] = {acc.x * inv, acc.y * inv, acc.z * inv, acc.w * inv};
    int col = ((seg < n) ? 128 : 256) + lane * 4;
    split_store((size_t)node * K_DIM + col, vv);

    if (seg < n) {   // also convert this node's own x row (cols 0..127)
        float4 v = *(const float4*)&x[(size_t)node * IN_DIM + lane * 4];
        float xv[4] = {v.x, v.y, v.z, v.w};
        split_store((size_t)node * K_DIM + lane * 4, xv);
    }
}

// ---------------------------------------------------------------------------
// K6: W -> bf16 hi/lo.
// ---------------------------------------------------------------------------
__global__ void convert_W_kernel(const float* __restrict__ W)
{
    const size_t total = (size_t)K_DIM * OUT_DIM / 4;
    for (size_t i = (size_t)blockIdx.x * blockDim.x + threadIdx.x;
         i < total; i += (size_t)gridDim.x * blockDim.x) {
        float4 v = *(const float4*)&W[i * 4];
        float vv[4] = {v.x, v.y, v.z, v.w};
        __nv_bfloat16 h[4], l[4];
        #pragma unroll
        for (int e = 0; e < 4; e++) {
            h[e] = __float2bfloat16(vv[e]);
            l[e] = __float2bfloat16(vv[e] - __bfloat162float(h[e]));
        }
        *(uint2*)&g_Bhi[i * 4] = *(uint2*)h;
        *(uint2*)&g_Blo[i * 4] = *(uint2*)l;
    }
}

// ---------------------------------------------------------------------------
// K7: pipelined bf16x3 GEMM, 128x256 tiles, 512 threads (16 warps 4x4),
// warp tile 32x64, B-fragments processed in two 4-nj halves (reg pressure).
// ---------------------------------------------------------------------------
#define GBM 128
#define GBN 256
#define GBK 32
#define A_STRIDE 40       // 32 + 8 pad (bf16)
#define B_STRIDE 264      // 256 + 8 pad (bf16)

#define AH_OFF(st) ((st) * GBM * A_STRIDE)
#define AL_OFF(st) (2 * GBM * A_STRIDE + (st) * GBM * A_STRIDE)
#define BH_OFF(st) (4 * GBM * A_STRIDE + (st) * GBK * B_STRIDE)
#define BL_OFF(st) (4 * GBM * A_STRIDE + 2 * GBK * B_STRIDE + (st) * GBK * B_STRIDE)
#define SMEM_BF16_TOTAL (4 * GBM * A_STRIDE + 4 * GBK * B_STRIDE)   // 54272 bf16 = 108544 B

__device__ __forceinline__ uint32_t smem_u32(const void* p)
{
    return (uint32_t)__cvta_generic_to_shared(p);
}

__device__ __forceinline__ void cp16(uint32_t saddr, const void* g)
{
    asm volatile("cp.async.ca.shared.global [%0], [%1], 16;" :: "r"(saddr), "l"(g));
}

__device__ __forceinline__ void ldsm_x4(uint32_t& r0, uint32_t& r1,
                                        uint32_t& r2, uint32_t& r3, uint32_t addr)
{
    asm volatile("ldmatrix.sync.aligned.m8n8.x4.shared.b16 {%0,%1,%2,%3}, [%4];"
                 : "=r"(r0), "=r"(r1), "=r"(r2), "=r"(r3) : "r"(addr));
}

__device__ __forceinline__ void ldsm_x4_t(uint32_t& r0, uint32_t& r1,
                                          uint32_t& r2, uint32_t& r3, uint32_t addr)
{
    asm volatile("ldmatrix.sync.aligned.m8n8.x4.trans.shared.b16 {%0,%1,%2,%3}, [%4];"
                 : "=r"(r0), "=r"(r1), "=r"(r2), "=r"(r3) : "r"(addr));
}

__device__ __forceinline__ void mma_bf16(float c[4], const uint32_t a[4],
                                         const uint32_t b[2])
{
    asm volatile(
        "mma.sync.aligned.m16n8k16.row.col.f32.bf16.bf16.f32 "
        "{%0,%1,%2,%3}, {%4,%5,%6,%7}, {%8,%9}, {%0,%1,%2,%3};"
        : "+f"(c[0]), "+f"(c[1]), "+f"(c[2]), "+f"(c[3])
        : "r"(a[0]), "r"(a[1]), "r"(a[2]), "r"(a[3]), "r"(b[0]), "r"(b[1]));
}

__global__ __launch_bounds__(512, 1)
void gemm_kernel(const float* __restrict__ bias, float* __restrict__ out, int M)
{
    extern __shared__ __nv_bfloat16 smem[];
    const uint32_t sbase = smem_u32(smem);

    const int tid  = threadIdx.x;
    const int warp = tid >> 5;
    const int lane = tid & 31;
    const int wm = (warp >> 2) * 32;      // 4 M-warps
    const int wn = (warp & 3) * 64;       // 4 N-warps

    const int rowBase = blockIdx.y * GBM;
    const int colBase = blockIdx.x * GBN;

    float acc[2][8][4];
    #pragma unroll
    for (int i = 0; i < 2; i++)
        #pragma unroll
        for (int j = 0; j < 8; j++)
            #pragma unroll
            for (int c = 0; c < 4; c++) acc[i][j][c] = 0.f;

    auto load_stage = [&](int st, int k0) {
        {   // A: 128 rows x 4 chunks of 16B = 512 chunks, 1/thread
            int r = tid >> 2, o = (tid & 3) * 8;
            size_t gofs = (size_t)(rowBase + r) * K_DIM + k0 + o;
            cp16(sbase + (AH_OFF(st) + r * A_STRIDE + o) * 2, &g_Ahi[gofs]);
            cp16(sbase + (AL_OFF(st) + r * A_STRIDE + o) * 2, &g_Alo[gofs]);
        }
        #pragma unroll
        for (int it = 0; it < 2; it++) {   // B: 32 rows x 32 chunks = 1024, 2/thread
            int c = tid + it * 512;
            int r = c >> 5, o = (c & 31) * 8;
            size_t gofs = (size_t)(k0 + r) * OUT_DIM + colBase + o;
            cp16(sbase + (BH_OFF(st) + r * B_STRIDE + o) * 2, &g_Bhi[gofs]);
            cp16(sbase + (BL_OFF(st) + r * B_STRIDE + o) * 2, &g_Blo[gofs]);
        }
        asm volatile("cp.async.commit_group;");
    };

    const int a_row  = lane & 15;
    const int a_koff = (lane >> 4) * 8;
    const int b_k    = lane & 15;
    const int b_noff = (lane >> 4) * 8;

    load_stage(0, 0);

    const int NITER = K_DIM / GBK;        // 12
    for (int itr = 0; itr < NITER; itr++) {
        if (itr + 1 < NITER) {
            load_stage((itr + 1) & 1, (itr + 1) * GBK);
            asm volatile("cp.async.wait_group 1;");
        } else {
            asm volatile("cp.async.wait_group 0;");
        }
        __syncthreads();

        const int st = itr & 1;
        const __nv_bfloat16* Ah = smem + AH_OFF(st);
        const __nv_bfloat16* Al = smem + AL_OFF(st);
        const __nv_bfloat16* Bh = smem + BH_OFF(st);
        const __nv_bfloat16* Bl = smem + BL_OFF(st);

        #pragma unroll
        for (int kk = 0; kk < GBK; kk += 16) {
            uint32_t ah[2][4], al[2][4];
            #pragma unroll
            for (int mi = 0; mi < 2; mi++) {
                int row = wm + mi * 16 + a_row;
                ldsm_x4(ah[mi][0], ah[mi][1], ah[mi][2], ah[mi][3],
                        smem_u32(Ah + row * A_STRIDE + kk + a_koff));
                ldsm_x4(al[mi][0], al[mi][1], al[mi][2], al[mi][3],
                        smem_u32(Al + row * A_STRIDE + kk + a_koff));
            }
            #pragma unroll
            for (int h = 0; h < 2; h++) {          // two 4-nj halves (reg pressure)
                uint32_t bh[4][2], bl[4][2];
                #pragma unroll
                for (int njp = 0; njp < 2; njp++) {
                    uint32_t r0, r1, r2, r3;
                    int cofs = wn + h * 32 + njp * 16 + b_noff;
                    ldsm_x4_t(r0, r1, r2, r3,
                              smem_u32(Bh + (kk + b_k) * B_STRIDE + cofs));
                    bh[njp*2][0] = r0; bh[njp*2][1] = r1;
                    bh[njp*2+1][0] = r2; bh[njp*2+1][1] = r3;
                    ldsm_x4_t(r0, r1, r2, r3,
                              smem_u32(Bl + (kk + b_k) * B_STRIDE + cofs));
                    bl[njp*2][0] = r0; bl[njp*2][1] = r1;
                    bl[njp*2+1][0] = r2; bl[njp*2+1][1] = r3;
                }
                #pragma unroll
                for (int mi = 0; mi < 2; mi++)
                    #pragma unroll
                    for (int nje = 0; nje < 4; nje++) {
                        float* a4 = acc[mi][h * 4 + nje];
                        mma_bf16(a4, ah[mi], bh[nje]);
                        mma_bf16(a4, ah[mi], bl[nje]);
                        mma_bf16(a4, al[mi], bh[nje]);
                    }
            }
        }
        __syncthreads();
    }

    // epilogue
    const int g = lane >> 2;
    const int t = lane & 3;
    #pragma unroll
    for (int mi = 0; mi < 2; mi++) {
        int r0 = rowBase + wm + mi * 16 + g;
        int r1 = r0 + 8;
        #pragma unroll
        for (int nj = 0; nj < 8; nj++) {
            int c = colBase + wn + nj * 8 + t * 2;
            float2 bv = *(const float2*)&bias[c];
            if (r0 < M) {
                float2 o;
                o.x = fmaxf(acc[mi][nj][0] + bv.x, 0.f);
                o.y = fmaxf(acc[mi][nj][1] + bv.y, 0.f);
                *(float2*)&out[(size_t)r0 * OUT_DIM + c] = o;
            }
            if (r1 < M) {
                float2 o;
                o.x = fmaxf(acc[mi][nj][2] + bv.x, 0.f);
                o.y = fmaxf(acc[mi][nj][3] + bv.y, 0.f);
                *(float2*)&out[(size_t)r1 * OUT_DIM + c] = o;
            }
        }
    }
}

// ---------------------------------------------------------------------------
// launch
// ---------------------------------------------------------------------------
extern "C" void kernel_launch(void* const* d_in, const int* in_sizes, int n_in,
                              void* d_out, int out_size)
{
    const float* x = (const float*)d_in[0];
    const int n = in_sizes[0] / IN_DIM;
    float* out = (float*)d_out;

    const float* W;
    const float* b;
    const void* src_buf;
    const void* dst_buf;
    int E;

    if (n_in >= 5) {
        E = in_sizes[1];
        src_buf = d_in[1];
        dst_buf = d_in[2];
        W = (const float*)d_in[3];
        b = (const float*)d_in[4];
    } else {
        E = in_sizes[1] / 2;
        src_buf = d_in[1];
        dst_buf = nullptr;
        W = (const float*)d_in[2];
        b = (const float*)d_in[3];
    }

    const int total = 2 * n;
    const int scan_blocks = (total + SCAN_BS - 1) / SCAN_BS;

    {
        size_t work = (size_t)(M_PAD - N_MAX) * K_DIM / 8;
        if ((size_t)total > work) work = total;
        zero_detect_kernel<<<(int)((work + 255) / 256), 256>>>(
            (const long long*)d_in[1], n, E);
    }
    hist_kernel<<<(E + 255) / 256, 256>>>(src_buf, dst_buf, n, E);
    scan1_kernel<<<scan_blocks, SCAN_BS>>>(total);
    scan2_kernel<<<1, 256>>>(scan_blocks);
    scan3_kernel<<<scan_blocks, SCAN_BS>>>(total, 2 * E);
    fill_kernel<<<(E + 255) / 256, 256>>>(src_buf, dst_buf, n, E);
    {
        long long threads = (long long)total * 32;
        gather_kernel<<<(int)((threads + 255) / 256), 256>>>(x, n);
    }
    convert_W_kernel<<<384, 256>>>(W);
    {
        static const int smem_bytes = SMEM_BF16_TOTAL * 2;   // 108544
        cudaFuncSetAttribute(gemm_kernel,
                             cudaFuncAttributeMaxDynamicSharedMemorySize, smem_bytes);
        dim3 grid(OUT_DIM / GBN, M_PAD / GBM);
        gemm_kernel<<<grid, 512, smem_bytes>>>(b, out, n);
    }
}